// round 12
// baseline (speedup 1.0000x reference)
#include <cuda_runtime.h>
#include <utility>
#include <cstddef>

// ============================================================================
// SO(3) tensor product: out[n,c,k] = sum_{i,j} cg[i,j,k] * x[n,c,i] * y[n,c,j]
// CG coefficients are compile-time constants (FFMA immediates).
// R11: register-pressure cut. Each 32-k pass is computed as two independent
// 16-k half-stages (16 live accumulators instead of 32), retiring straight
// into STS.128. __launch_bounds__(128, 7) raises the occupancy ceiling from
// 31% to 44%. Warp-local double-buffered smem + static drain unchanged.
// ============================================================================

namespace tp {

struct CGE { int i; int j; int k; float v; };

__host__ __device__ constexpr double cfact(int n) {
    double r = 1.0;
    for (int i = 2; i <= n; ++i) r *= (double)i;
    return r;
}

__host__ __device__ constexpr double csqrt(double x) {
    if (x <= 0.0) return 0.0;
    double g = x < 1.0 ? 1.0 : x;
    for (int it = 0; it < 48; ++it) g = 0.5 * (g + x / g);
    return g;
}

__host__ __device__ constexpr double w3j(int j1, int j2, int j3,
                                         int m1, int m2, int m3) {
    if (m1 + m2 + m3 != 0) return 0.0;
    int dlo = j1 > j2 ? j1 - j2 : j2 - j1;
    if (j3 < dlo || j3 > j1 + j2) return 0.0;
    int t1 = j2 - m1 - j3;
    int t2 = j1 + m2 - j3;
    int t3 = j1 + j2 - j3;
    int t4 = j1 - m1;
    int t5 = j2 + m2;
    int tmin = 0; if (t1 > tmin) tmin = t1; if (t2 > tmin) tmin = t2;
    int tmax = t3; if (t4 < tmax) tmax = t4; if (t5 < tmax) tmax = t5;
    if (tmin > tmax) return 0.0;
    double s = 0.0;
    for (int t = tmin; t <= tmax; ++t) {
        double term = 1.0 / (cfact(t) * cfact(t - t1) * cfact(t - t2)
                             * cfact(t3 - t) * cfact(t4 - t) * cfact(t5 - t));
        if (t & 1) term = -term;
        s += term;
    }
    double pref = csqrt(
        cfact(j1 + j2 - j3) * cfact(j1 - j2 + j3) * cfact(-j1 + j2 + j3)
        / cfact(j1 + j2 + j3 + 1)
        * cfact(j1 + m1) * cfact(j1 - m1)
        * cfact(j2 + m2) * cfact(j2 - m2)
        * cfact(j3 + m3) * cfact(j3 - m3));
    int ex = j1 - j2 - m3;
    if (ex % 2 != 0) pref = -pref;
    return pref * s;
}

__host__ __device__ constexpr int cg_count_below(int K) {
    int n = 0;
    int off = 0;
    for (int l1 = 0; l1 <= 3; ++l1)
    for (int l2 = 0; l2 <= 3; ++l2) {
        int lo = l1 > l2 ? l1 - l2 : l2 - l1;
        int hi = (l1 + l2) < 3 ? (l1 + l2) : 3;
        for (int l3 = lo; l3 <= hi; ++l3) {
            for (int m3 = -l3; m3 <= l3; ++m3) {
                int k = off + m3 + l3;
                if (k < K) {
                    for (int m1 = -l1; m1 <= l1; ++m1) {
                        int m2 = -m1 - m3;
                        if (m2 < -l2 || m2 > l2) continue;
                        double w = w3j(l1, l2, l3, m1, m2, m3);
                        if (w > 1e-12 || w < -1e-12) ++n;
                    }
                }
            }
            off += 2 * l3 + 1;
        }
    }
    return n;
}

__host__ __device__ constexpr CGE cg_entry(int idx) {
    int n = 0;
    int off = 0;
    for (int l1 = 0; l1 <= 3; ++l1)
    for (int l2 = 0; l2 <= 3; ++l2) {
        int lo = l1 > l2 ? l1 - l2 : l2 - l1;
        int hi = (l1 + l2) < 3 ? (l1 + l2) : 3;
        for (int l3 = lo; l3 <= hi; ++l3) {
            for (int m3 = -l3; m3 <= l3; ++m3) {
                int k = off + m3 + l3;
                for (int m1 = -l1; m1 <= l1; ++m1) {
                    int m2 = -m1 - m3;
                    if (m2 < -l2 || m2 > l2) continue;
                    double w = w3j(l1, l2, l3, m1, m2, m3);
                    if (w > 1e-12 || w < -1e-12) {
                        if (n == idx) return CGE{m1 + l1, m2 + l2, k, (float)w};
                        ++n;
                    }
                }
            }
            off += 2 * l3 + 1;
        }
    }
    return CGE{0, 0, 0, 0.0f};
}

constexpr int DIM_OUT  = 156;
constexpr int DIM_OUT4 = DIM_OUT / 4;   // 39
constexpr int TPB   = 128;
constexpr int WARPS = TPB / 32;

template <int E, int K0>
__device__ __forceinline__ void term(const float* xr, const float* yr, float* acc) {
    constexpr CGE e = cg_entry(E);   // compile-time: immediate coefficient
    acc[e.k - K0] = fmaf(e.v, xr[e.i] * yr[e.j], acc[e.k - K0]);
}

template <int K0, int E0, size_t... Is>
__device__ __forceinline__ void terms(std::index_sequence<Is...>,
                                      const float* xr, const float* yr, float* acc) {
    (term<E0 + (int)Is, K0>(xr, yr, acc), ...);
}

// Half-stage: compute KH (<=16) outputs starting at global k index KH0 and
// retire them immediately into STS.128 at float4 slots [Q0, Q0+KH/4) of this
// lane's buffer row. Only KH accumulators are ever live.
template <int KH0, int KH, int Q0>
__device__ __forceinline__ void half_stage(const float* xr, const float* yr,
                                           float4* wbuf, int lane) {
    float acc[KH] = {};
    constexpr int E0 = cg_count_below(KH0);
    constexpr int E1 = cg_count_below(KH0 + KH);
    terms<KH0, E0>(std::make_index_sequence<(size_t)(E1 - E0)>{}, xr, yr, acc);
    constexpr int VH = KH / 4;
    #pragma unroll
    for (int v = 0; v < VH; ++v) {
        int q = Q0 + v;
        wbuf[lane * 8 + (q ^ (lane & 7))] =
            make_float4(acc[4 * v + 0], acc[4 * v + 1], acc[4 * v + 2], acc[4 * v + 3]);
    }
}

// Full 32-k stage as two independent 16-k half-stages (halves live registers).
template <int K0>
__device__ __forceinline__ void stage32(const float* xr, const float* yr,
                                        float4* wbuf, int lane) {
    half_stage<K0,      16, 0>(xr, yr, wbuf, lane);
    half_stage<K0 + 16, 16, 4>(xr, yr, wbuf, lane);
}

// Last stage: 28 k = 16 + 12.
template <int K0>
__device__ __forceinline__ void stage28(const float* xr, const float* yr,
                                        float4* wbuf, int lane) {
    half_stage<K0,      16, 0>(xr, yr, wbuf, lane);
    half_stage<K0 + 16, 12, 4>(xr, yr, wbuf, lane);
}

// Drain the warp's 32x8 float4 tile: fully static indices, 8 independent
// LDS.128 -> STG.128 chains. wbase4 = first output float4 of this warp's pairs.
template <int K0>
__device__ __forceinline__ void drain32(const float4* wbuf, float4* __restrict__ out4,
                                        size_t wbase4, int lane) {
    const int q = lane & 7;
    const int pl = lane >> 3;
    #pragma unroll
    for (int u = 0; u < 8; ++u) {
        int p = pl + 4 * u;
        float4 v = wbuf[p * 8 + (q ^ (p & 7))];
        __stcs(&out4[wbase4 + (size_t)p * DIM_OUT4 + (K0 / 4) + q], v);
    }
}

// Drain 32x7 float4 (last pass, KPP=28).
template <int K0>
__device__ __forceinline__ void drain28(const float4* wbuf, float4* __restrict__ out4,
                                        size_t wbase4, int lane) {
    #pragma unroll
    for (int u = 0; u < 7; ++u) {
        int g = lane + 32 * u;
        int p = g / 7;                     // const div -> IMAD magic number
        int q = g - p * 7;
        float4 v = wbuf[p * 8 + (q ^ (p & 7))];
        __stcs(&out4[wbase4 + (size_t)p * DIM_OUT4 + (K0 / 4) + q], v);
    }
}

// -------- tail path (only last partial block): guarded, block barriers --------
template <int K0, int KPP>
__device__ __forceinline__ void pass_tail(const float* xr, const float* yr,
                                          float4* buf, float4* __restrict__ out4,
                                          size_t base4, int tid, int validPairs) {
    float acc[KPP] = {};
    constexpr int E0 = cg_count_below(K0);
    constexpr int E1 = cg_count_below(K0 + KPP);
    terms<K0, E0>(std::make_index_sequence<(size_t)(E1 - E0)>{}, xr, yr, acc);
    constexpr int V = KPP / 4;
    #pragma unroll
    for (int q = 0; q < V; ++q)
        buf[tid * 8 + (q ^ (tid & 7))] =
            make_float4(acc[4 * q + 0], acc[4 * q + 1], acc[4 * q + 2], acc[4 * q + 3]);
    __syncthreads();
    int tot4 = validPairs * V;
    for (int g4 = tid; g4 < tot4; g4 += TPB) {
        int p = g4 / V;
        int q = g4 - p * V;
        float4 v = buf[p * 8 + (q ^ (p & 7))];
        out4[base4 + (size_t)p * DIM_OUT4 + (K0 / 4) + q] = v;
    }
    __syncthreads();
}

__global__ void __launch_bounds__(TPB, 7)
tp_kernel(const float* __restrict__ x, const float* __restrict__ y,
          float* __restrict__ out, int npairs) {
    // Per-warp double buffer: [2 buffers][4 warps][32 pairs * 8 float4] = 32 KB.
    __shared__ float4 buf[2 * WARPS * 256];
    const int tid  = threadIdx.x;
    const int lane = tid & 31;
    const int w    = tid >> 5;
    const bool full = (blockIdx.x + 1) * TPB <= npairs;   // block-uniform

    float4* out4 = reinterpret_cast<float4*>(out);

    if (full) {
        float4* wbufA = buf + w * 256;
        float4* wbufB = buf + WARPS * 256 + w * 256;

        const int pair0 = blockIdx.x * TPB + w * 32;      // warp's first pair
        const size_t wbase4 = (size_t)pair0 * DIM_OUT4;

        // Warp-local input staging: 56 float4 of x, 56 of y (896 B each,
        // float4-aligned since pair0 % 32 == 0).
        const float4* x4 = reinterpret_cast<const float4*>(x + (size_t)pair0 * 7);
        const float4* y4 = reinterpret_cast<const float4*>(y + (size_t)pair0 * 7);
        wbufA[lane]      = x4[lane];
        wbufA[56 + lane] = y4[lane];
        if (lane < 24) {
            wbufA[32 + lane] = x4[32 + lane];
            wbufA[88 + lane] = y4[32 + lane];
        }
        __syncwarp();

        float xr[7], yr[7];
        const float* bf = reinterpret_cast<const float*>(wbufA);
        #pragma unroll
        for (int i = 0; i < 7; ++i) {     // 7*lane mod 32 bijective: conflict-free
            xr[i] = bf[lane * 7 + i];
            yr[i] = bf[224 + lane * 7 + i];
        }
        __syncwarp();

        // Software-pipelined passes: drain(N) and compute+stage(N+1) share a
        // syncwarp interval -> LDS/STG latency hidden under FFMAs.
        stage32<0>(xr, yr, wbufB, lane);
        __syncwarp();
        stage32<32>(xr, yr, wbufA, lane);
        drain32<0>(wbufB, out4, wbase4, lane);
        __syncwarp();
        stage32<64>(xr, yr, wbufB, lane);
        drain32<32>(wbufA, out4, wbase4, lane);
        __syncwarp();
        stage32<96>(xr, yr, wbufA, lane);
        drain32<64>(wbufB, out4, wbase4, lane);
        __syncwarp();
        stage28<128>(xr, yr, wbufB, lane);
        drain32<96>(wbufA, out4, wbase4, lane);
        __syncwarp();
        drain28<128>(wbufB, out4, wbase4, lane);
    } else {
        float xr[7], yr[7];
        int pair = blockIdx.x * TPB + tid;
        if (pair < npairs) {
            const float* xp = x + (size_t)pair * 7;
            const float* yp = y + (size_t)pair * 7;
            #pragma unroll
            for (int i = 0; i < 7; ++i) { xr[i] = __ldg(xp + i); yr[i] = __ldg(yp + i); }
        } else {
            #pragma unroll
            for (int i = 0; i < 7; ++i) { xr[i] = 0.0f; yr[i] = 0.0f; }
        }
        int validPairs = npairs - blockIdx.x * TPB;
        const size_t base4 = (size_t)blockIdx.x * (TPB * DIM_OUT4);
        pass_tail<0,   32>(xr, yr, buf, out4, base4, tid, validPairs);
        pass_tail<32,  32>(xr, yr, buf, out4, base4, tid, validPairs);
        pass_tail<64,  32>(xr, yr, buf, out4, base4, tid, validPairs);
        pass_tail<96,  32>(xr, yr, buf, out4, base4, tid, validPairs);
        pass_tail<128, 28>(xr, yr, buf, out4, base4, tid, validPairs);
    }
}

}  // namespace tp

extern "C" void kernel_launch(void* const* d_in, const int* in_sizes, int n_in,
                              void* d_out, int out_size) {
    (void)n_in; (void)out_size;
    const float* x = (const float*)d_in[0];
    const float* y = (const float*)d_in[1];
    float* out = (float*)d_out;
    int npairs = in_sizes[0] / 7;               // E * C
    int blocks = (npairs + tp::TPB - 1) / tp::TPB;
    tp::tp_kernel<<<blocks, tp::TPB>>>(x, y, out, npairs);
}

// round 17
// speedup vs baseline: 1.6620x; 1.6620x over previous
#include <cuda_runtime.h>
#include <cstdint>
#include <utility>
#include <cstddef>

// ============================================================================
// SO(3) tensor product: out[n,c,k] = sum_{i,j} cg[i,j,k] * x[n,c,i] * y[n,c,j]
// CG coefficients are compile-time constants (FFMA immediates).
// R16 (= R12 + <cstdint> fix): TMA bulk stores. Each block stages its full
// [128 x 156] f32 output tile contiguously in dynamic smem (row stride 39
// float4 -> odd -> conflict-free STS.128, no swizzle, no LDS drain), then each
// warp fires ONE cp.async.bulk shared->global (19968 B) for its 32 contiguous
// rows. Stores bypass the LSU entirely; only lane 0 of each warp waits.
// ============================================================================

namespace tp {

struct CGE { int i; int j; int k; float v; };

__host__ __device__ constexpr double cfact(int n) {
    double r = 1.0;
    for (int i = 2; i <= n; ++i) r *= (double)i;
    return r;
}

__host__ __device__ constexpr double csqrt(double x) {
    if (x <= 0.0) return 0.0;
    double g = x < 1.0 ? 1.0 : x;
    for (int it = 0; it < 48; ++it) g = 0.5 * (g + x / g);
    return g;
}

__host__ __device__ constexpr double w3j(int j1, int j2, int j3,
                                         int m1, int m2, int m3) {
    if (m1 + m2 + m3 != 0) return 0.0;
    int dlo = j1 > j2 ? j1 - j2 : j2 - j1;
    if (j3 < dlo || j3 > j1 + j2) return 0.0;
    int t1 = j2 - m1 - j3;
    int t2 = j1 + m2 - j3;
    int t3 = j1 + j2 - j3;
    int t4 = j1 - m1;
    int t5 = j2 + m2;
    int tmin = 0; if (t1 > tmin) tmin = t1; if (t2 > tmin) tmin = t2;
    int tmax = t3; if (t4 < tmax) tmax = t4; if (t5 < tmax) tmax = t5;
    if (tmin > tmax) return 0.0;
    double s = 0.0;
    for (int t = tmin; t <= tmax; ++t) {
        double term = 1.0 / (cfact(t) * cfact(t - t1) * cfact(t - t2)
                             * cfact(t3 - t) * cfact(t4 - t) * cfact(t5 - t));
        if (t & 1) term = -term;
        s += term;
    }
    double pref = csqrt(
        cfact(j1 + j2 - j3) * cfact(j1 - j2 + j3) * cfact(-j1 + j2 + j3)
        / cfact(j1 + j2 + j3 + 1)
        * cfact(j1 + m1) * cfact(j1 - m1)
        * cfact(j2 + m2) * cfact(j2 - m2)
        * cfact(j3 + m3) * cfact(j3 - m3));
    int ex = j1 - j2 - m3;
    if (ex % 2 != 0) pref = -pref;
    return pref * s;
}

__host__ __device__ constexpr int cg_count_below(int K) {
    int n = 0;
    int off = 0;
    for (int l1 = 0; l1 <= 3; ++l1)
    for (int l2 = 0; l2 <= 3; ++l2) {
        int lo = l1 > l2 ? l1 - l2 : l2 - l1;
        int hi = (l1 + l2) < 3 ? (l1 + l2) : 3;
        for (int l3 = lo; l3 <= hi; ++l3) {
            for (int m3 = -l3; m3 <= l3; ++m3) {
                int k = off + m3 + l3;
                if (k < K) {
                    for (int m1 = -l1; m1 <= l1; ++m1) {
                        int m2 = -m1 - m3;
                        if (m2 < -l2 || m2 > l2) continue;
                        double w = w3j(l1, l2, l3, m1, m2, m3);
                        if (w > 1e-12 || w < -1e-12) ++n;
                    }
                }
            }
            off += 2 * l3 + 1;
        }
    }
    return n;
}

__host__ __device__ constexpr CGE cg_entry(int idx) {
    int n = 0;
    int off = 0;
    for (int l1 = 0; l1 <= 3; ++l1)
    for (int l2 = 0; l2 <= 3; ++l2) {
        int lo = l1 > l2 ? l1 - l2 : l2 - l1;
        int hi = (l1 + l2) < 3 ? (l1 + l2) : 3;
        for (int l3 = lo; l3 <= hi; ++l3) {
            for (int m3 = -l3; m3 <= l3; ++m3) {
                int k = off + m3 + l3;
                for (int m1 = -l1; m1 <= l1; ++m1) {
                    int m2 = -m1 - m3;
                    if (m2 < -l2 || m2 > l2) continue;
                    double w = w3j(l1, l2, l3, m1, m2, m3);
                    if (w > 1e-12 || w < -1e-12) {
                        if (n == idx) return CGE{m1 + l1, m2 + l2, k, (float)w};
                        ++n;
                    }
                }
            }
            off += 2 * l3 + 1;
        }
    }
    return CGE{0, 0, 0, 0.0f};
}

constexpr int DIM_OUT  = 156;
constexpr int DIM_OUT4 = DIM_OUT / 4;       // 39
constexpr int TPB   = 128;
constexpr int WARPS = TPB / 32;
constexpr int WARP_TILE_BYTES  = 32 * DIM_OUT * 4;          // 19968
constexpr int BLOCK_TILE_BYTES = TPB * DIM_OUT * 4;         // 79872
constexpr int WARP_TILE_FLOATS = 32 * DIM_OUT;              // 4992

template <int E, int K0>
__device__ __forceinline__ void term(const float* xr, const float* yr, float* acc) {
    constexpr CGE e = cg_entry(E);   // compile-time: immediate coefficient
    acc[e.k - K0] = fmaf(e.v, xr[e.i] * yr[e.j], acc[e.k - K0]);
}

template <int K0, int E0, size_t... Is>
__device__ __forceinline__ void terms(std::index_sequence<Is...>,
                                      const float* xr, const float* yr, float* acc) {
    (term<E0 + (int)Is, K0>(xr, yr, acc), ...);
}

// Compute outputs [K0, K0+KH) for this thread's pair and retire straight into
// the thread's contiguous smem row via STS.128 (row stride 39 float4, odd ->
// conflict-free within every 8-lane phase).
template <int K0, int KH>
__device__ __forceinline__ void stage_sts(const float* xr, const float* yr,
                                          float* row) {
    float acc[KH] = {};
    constexpr int E0 = cg_count_below(K0);
    constexpr int E1 = cg_count_below(K0 + KH);
    terms<K0, E0>(std::make_index_sequence<(size_t)(E1 - E0)>{}, xr, yr, acc);
    float4* r4 = reinterpret_cast<float4*>(row);
    #pragma unroll
    for (int v = 0; v < KH / 4; ++v)
        r4[K0 / 4 + v] = make_float4(acc[4 * v + 0], acc[4 * v + 1],
                                     acc[4 * v + 2], acc[4 * v + 3]);
}

__device__ __forceinline__ unsigned int smem_u32(const void* p) {
    unsigned int a;
    asm("{ .reg .u64 t; cvta.to.shared.u64 t, %1; cvt.u32.u64 %0, t; }"
        : "=r"(a) : "l"(p));
    return a;
}

// Tail: compute KH outputs and STG them directly (only last partial block).
template <int K0, int KH>
__device__ __forceinline__ void stage_stg(const float* xr, const float* yr,
                                          float4* __restrict__ dst4) {
    float acc[KH] = {};
    constexpr int E0 = cg_count_below(K0);
    constexpr int E1 = cg_count_below(K0 + KH);
    terms<K0, E0>(std::make_index_sequence<(size_t)(E1 - E0)>{}, xr, yr, acc);
    #pragma unroll
    for (int v = 0; v < KH / 4; ++v)
        dst4[K0 / 4 + v] = make_float4(acc[4 * v + 0], acc[4 * v + 1],
                                       acc[4 * v + 2], acc[4 * v + 3]);
}

__global__ void __launch_bounds__(TPB)
tp_kernel(const float* __restrict__ x, const float* __restrict__ y,
          float* __restrict__ out, int npairs) {
    extern __shared__ float smemf[];               // BLOCK_TILE_BYTES dynamic
    const int tid  = threadIdx.x;
    const int lane = tid & 31;
    const int w    = tid >> 5;
    const bool full = (blockIdx.x + 1) * TPB <= npairs;   // block-uniform

    if (full) {
        float* wreg = smemf + w * WARP_TILE_FLOATS;       // warp's 19968B region
        const int pair0 = blockIdx.x * TPB + w * 32;      // warp's first pair

        // ---- warp-local input staging into (soon overwritten) tile region ----
        const float4* x4 = reinterpret_cast<const float4*>(x + (size_t)pair0 * 7);
        const float4* y4 = reinterpret_cast<const float4*>(y + (size_t)pair0 * 7);
        float4* wb = reinterpret_cast<float4*>(wreg);
        wb[lane]      = x4[lane];
        wb[56 + lane] = y4[lane];
        if (lane < 24) {
            wb[32 + lane] = x4[32 + lane];
            wb[88 + lane] = y4[32 + lane];
        }
        __syncwarp();

        float xr[7], yr[7];
        #pragma unroll
        for (int i = 0; i < 7; ++i) {      // 7*lane mod 32 bijective: conflict-free
            xr[i] = wreg[lane * 7 + i];
            yr[i] = wreg[224 + lane * 7 + i];
        }
        __syncwarp();                      // all reads done before rows overwrite

        // ---- compute + stage full 156-float row (10 register passes) ----
        float* row = wreg + lane * DIM_OUT;
        stage_sts<0,   16>(xr, yr, row);
        stage_sts<16,  16>(xr, yr, row);
        stage_sts<32,  16>(xr, yr, row);
        stage_sts<48,  16>(xr, yr, row);
        stage_sts<64,  16>(xr, yr, row);
        stage_sts<80,  16>(xr, yr, row);
        stage_sts<96,  16>(xr, yr, row);
        stage_sts<112, 16>(xr, yr, row);
        stage_sts<128, 16>(xr, yr, row);
        stage_sts<144, 12>(xr, yr, row);
        __syncwarp();

        // ---- one bulk async store for the warp's 32 contiguous rows ----
        if (lane == 0) {
            float* gdst = out + (size_t)pair0 * DIM_OUT;
            unsigned int saddr = smem_u32(wreg);
            asm volatile("fence.proxy.async.shared::cta;" ::: "memory");
            asm volatile(
                "cp.async.bulk.global.shared::cta.bulk_group [%0], [%1], %2;"
                :: "l"(gdst), "r"(saddr), "r"((unsigned int)WARP_TILE_BYTES)
                : "memory");
            asm volatile("cp.async.bulk.commit_group;" ::: "memory");
            // Block smem must stay live until the bulk engine has READ it.
            asm volatile("cp.async.bulk.wait_group.read 0;" ::: "memory");
        }
    } else {
        // ---- tail: guarded per-thread direct stores (at most one block) ----
        int pair = blockIdx.x * TPB + tid;
        if (pair < npairs) {
            float xr[7], yr[7];
            const float* xp = x + (size_t)pair * 7;
            const float* yp = y + (size_t)pair * 7;
            #pragma unroll
            for (int i = 0; i < 7; ++i) { xr[i] = __ldg(xp + i); yr[i] = __ldg(yp + i); }
            float4* dst4 = reinterpret_cast<float4*>(out) + (size_t)pair * DIM_OUT4;
            stage_stg<0,   16>(xr, yr, dst4);
            stage_stg<16,  16>(xr, yr, dst4);
            stage_stg<32,  16>(xr, yr, dst4);
            stage_stg<48,  16>(xr, yr, dst4);
            stage_stg<64,  16>(xr, yr, dst4);
            stage_stg<80,  16>(xr, yr, dst4);
            stage_stg<96,  16>(xr, yr, dst4);
            stage_stg<112, 16>(xr, yr, dst4);
            stage_stg<128, 16>(xr, yr, dst4);
            stage_stg<144, 12>(xr, yr, dst4);
        }
    }
}

}  // namespace tp

extern "C" void kernel_launch(void* const* d_in, const int* in_sizes, int n_in,
                              void* d_out, int out_size) {
    (void)n_in; (void)out_size;
    const float* x = (const float*)d_in[0];
    const float* y = (const float*)d_in[1];
    float* out = (float*)d_out;
    int npairs = in_sizes[0] / 7;               // E * C
    int blocks = (npairs + tp::TPB - 1) / tp::TPB;
    cudaFuncSetAttribute(tp::tp_kernel,
                         cudaFuncAttributeMaxDynamicSharedMemorySize,
                         tp::BLOCK_TILE_BYTES);
    tp::tp_kernel<<<blocks, tp::TPB, tp::BLOCK_TILE_BYTES>>>(x, y, out, npairs);
}